// round 14
// baseline (speedup 1.0000x reference)
#include <cuda_runtime.h>
#include <cuda_bf16.h>
#include <cstdint>
#include <math.h>

typedef unsigned long long ull;
typedef __nv_bfloat16 bf16;

#define B_ROWS 4096
#define IN_F   1024
#define NLEAF  64
#define OUT_F  512
#define HK     4160                 /* 4096 H cols + 64 mixture cols (b2s fold) */
#define STAGE_BYTES 65536           /* Ah,Al,Bh,Bl tiles: 4 x 16KB per stage */
#define SMEMSZ (3*STAGE_BYTES)      /* 192KB, 1 CTA/SM */

// ---------------- device scratch ----------------
__device__ bf16 g_xh[B_ROWS*IN_F],  g_xl[B_ROWS*IN_F];
__device__ bf16 g_w1h[4096*1024],   g_w1l[4096*1024];   // [n=4096][k=1024]
__device__ bf16 g_w2h[512*HK],      g_w2l[512*HK];      // [o=512][k=4160]
__device__ bf16 g_Hh[(size_t)B_ROWS*HK], g_Hl[(size_t)B_ROWS*HK];
__device__ float g_mix[B_ROWS*NLEAF];

// ---------------- helpers ----------------
__device__ __forceinline__ void bsplit(float v, bf16 &h, bf16 &l){
    h = __float2bfloat16(v);
    l = __float2bfloat16(v - __bfloat162float(h));
}
__device__ __forceinline__ uint32_t s2u(const void* p){
    uint32_t a;
    asm("{ .reg .u64 t; cvta.to.shared.u64 t, %1; cvt.u32.u64 %0, t; }" : "=r"(a) : "l"(p));
    return a;
}
__device__ __forceinline__ void cpasync16(uint32_t dst, const void* src){
    asm volatile("cp.async.cg.shared.global [%0], [%1], 16;" :: "r"(dst), "l"(src) : "memory");
}
__device__ __forceinline__ void cp_commit(){ asm volatile("cp.async.commit_group;" ::: "memory"); }
__device__ __forceinline__ void ldsm4(uint32_t* r, uint32_t a){
    asm volatile("ldmatrix.sync.aligned.m8n8.x4.shared.b16 {%0,%1,%2,%3}, [%4];"
        : "=r"(r[0]), "=r"(r[1]), "=r"(r[2]), "=r"(r[3]) : "r"(a));
}
__device__ __forceinline__ void mma16816(float* c, const uint32_t* a, uint32_t b0, uint32_t b1){
    asm volatile("mma.sync.aligned.m16n8k16.row.col.f32.bf16.bf16.f32 "
        "{%0,%1,%2,%3}, {%4,%5,%6,%7}, {%8,%9}, {%0,%1,%2,%3};"
        : "+f"(c[0]), "+f"(c[1]), "+f"(c[2]), "+f"(c[3])
        : "r"(a[0]), "r"(a[1]), "r"(a[2]), "r"(a[3]), "r"(b0), "r"(b1));
}

// =====================================================================
// Merged conversion kernel for WEIGHTS (x conversion folded into mix).
// blocks [0,1024): convw1 | [1024,1536): convw2 | [1536,1544): convtail
// =====================================================================
__global__ __launch_bounds__(256) void conv_kernel(
    const float* __restrict__ w1, const float* __restrict__ w2,
    const float* __restrict__ b2)
{
    __shared__ float s[64][65];
    const int blk = blockIdx.x, tid = threadIdx.x;

    if (blk < 1024){                       // ---- convw1: [64,1024,64] -> [n][k] ----
        const int kc = blk & 15, l = blk >> 4;
        const float* src = w1 + ((size_t)l*1024 + kc*64)*64;
        for (int u = tid; u < 4096; u += 256) s[u>>6][u&63] = src[u];
        __syncthreads();
        const int w = tid>>2, i0 = (tid&3)*16;
        __align__(16) bf16 hh[16], ll[16];
#pragma unroll
        for (int i=0;i<16;i++) bsplit(s[i0+i][w], hh[i], ll[i]);
        size_t off = (size_t)(l*64+w)*1024 + kc*64 + i0;
        *(uint4*)&g_w1h[off]   = ((uint4*)hh)[0]; *(uint4*)&g_w1h[off+8] = ((uint4*)hh)[1];
        *(uint4*)&g_w1l[off]   = ((uint4*)ll)[0]; *(uint4*)&g_w1l[off+8] = ((uint4*)ll)[1];
        return;
    }
    if (blk < 1536){                       // ---- convw2: [4096,512] -> [o][k] ----
        const int b = blk - 1024, ot = b & 7, rt = b >> 3;
        for (int u = tid; u < 4096; u += 256)
            s[u>>6][u&63] = w2[(size_t)(rt*64 + (u>>6))*512 + ot*64 + (u&63)];
        __syncthreads();
        const int o = tid>>2, i0 = (tid&3)*16;
        __align__(16) bf16 hh[16], ll[16];
#pragma unroll
        for (int i=0;i<16;i++) bsplit(s[i0+i][o], hh[i], ll[i]);
        size_t off = (size_t)(ot*64+o)*HK + rt*64 + i0;
        *(uint4*)&g_w2h[off]   = ((uint4*)hh)[0]; *(uint4*)&g_w2h[off+8] = ((uint4*)hh)[1];
        *(uint4*)&g_w2l[off]   = ((uint4*)ll)[0]; *(uint4*)&g_w2l[off+8] = ((uint4*)ll)[1];
        return;
    }
    {                                      // ---- convtail: b2 [64,512] -> w2t[o][4096+j] ----
        const int ot = blk - 1536;
        for (int u = tid; u < 4096; u += 256)
            s[u>>6][u&63] = b2[(size_t)(u>>6)*512 + ot*64 + (u&63)];
        __syncthreads();
        const int o = tid>>2, j0 = (tid&3)*16;
        __align__(16) bf16 hh[16], ll[16];
#pragma unroll
        for (int i=0;i<16;i++) bsplit(s[j0+i][o], hh[i], ll[i]);
        size_t off = (size_t)(ot*64+o)*HK + 4096 + j0;
        *(uint4*)&g_w2h[off]   = ((uint4*)hh)[0]; *(uint4*)&g_w2h[off+8] = ((uint4*)hh)[1];
        *(uint4*)&g_w2l[off]   = ((uint4*)ll)[0]; *(uint4*)&g_w2l[off+8] = ((uint4*)ll)[1];
    }
}

// =====================================================================
// Routing tree + convx fold: 8 batch rows/block. Writes g_mix, the hi/lo
// mixture tail of H, AND g_xh/g_xl for its rows (x already staged in smem).
// =====================================================================
__global__ __launch_bounds__(256) void mix_kernel(
    const float* __restrict__ x, const float* __restrict__ nw, const float* __restrict__ nb)
{
    __shared__ float xs[8*1024];
    __shared__ float lg[8][64];
    const int tid = threadIdx.x, warp = tid>>5, lane = tid&31;
    const int b0 = blockIdx.x * 8;

    for (int u = tid; u < 2048; u += 256)
        ((float4*)xs)[u] = ((const float4*)(x + (size_t)b0*IN_F))[u];
    __syncthreads();

    // ---- convx fold: split this block's 8 rows to bf16 hi/lo ----
    for (int u = tid; u < 2048; u += 256){
        float4 v = ((const float4*)xs)[u];
        __align__(8) bf16 h[4], l[4];
        bsplit(v.x,h[0],l[0]); bsplit(v.y,h[1],l[1]); bsplit(v.z,h[2],l[2]); bsplit(v.w,h[3],l[3]);
        size_t off = (size_t)b0*IN_F + (size_t)u*4;
        *(ull*)&g_xh[off] = *(ull*)h;
        *(ull*)&g_xl[off] = *(ull*)l;
    }

    {
        float acc[8][8];
#pragma unroll
        for (int t=0;t<8;t++)
#pragma unroll
            for (int r=0;r<8;r++) acc[t][r] = 0.f;
        const float* wp[8];
#pragma unroll
        for (int t=0;t<8;t++){
            int nn = warp + 8*t;
            wp[t] = nw + (size_t)((nn < 63) ? nn : 0)*IN_F;
        }
        for (int j = 0; j < 32; ++j){
            const int o = lane + 32*j;
            float xv[8];
#pragma unroll
            for (int r=0;r<8;r++) xv[r] = xs[r*1024 + o];
#pragma unroll
            for (int t=0;t<8;t++){
                float wv = wp[t][o];
#pragma unroll
                for (int r=0;r<8;r++) acc[t][r] += xv[r]*wv;
            }
        }
#pragma unroll
        for (int t=0;t<8;t++){
            int nn = warp + 8*t;
#pragma unroll
            for (int r=0;r<8;r++){
                float s = acc[t][r];
#pragma unroll
                for (int o=16;o>0;o>>=1) s += __shfl_xor_sync(0xffffffffu, s, o);
                if (lane==0 && nn<63) lg[r][nn] = s + nb[nn];
            }
        }
    }
    __syncthreads();

#pragma unroll
    for (int p=0;p<2;p++){
        const int idx = tid + 256*p;
        const int r = idx>>6, l = idx&63;
        float m = 1.f;
#pragma unroll
        for (int d=0; d<6; ++d){
            int nidx = (1<<d) - 1 + (l >> (6-d));
            float sg = 1.f/(1.f + expf(-lg[r][nidx]));
            m *= ((l >> (5-d)) & 1) ? sg : (1.f - sg);
        }
        g_mix[(size_t)(b0+r)*NLEAF + l] = m;
        bf16 h, lo; bsplit(m, h, lo);
        g_Hh[(size_t)(b0+r)*HK + 4096 + l] = h;
        g_Hl[(size_t)(b0+r)*HK + 4096 + l] = lo;
    }
}

// =====================================================================
// HMMA split-bf16 GEMM (proven config + per-warp ks rotation): 512 threads,
// 16 warps (4 per SMSP), CTA tile 128x128, warp tile 32x32, BK=64, 3-stage
// 64KB pipeline. Warps sharing an SMSP (wid%4) start at different K16 steps
// ((wid>>2)&3) so ldsm bursts overlap SMSP-mates' mma phases.
// Per chunk: acc += Ah*Bh + Al*Bh + Ah*Bl.
// EPI 1: bias+relu+mix -> Hh/Hl bf16.   EPI 2: plain fp32 store.
// =====================================================================
template<int KTOT, int EPI>
__global__ __launch_bounds__(512,1) void gemm_mma(const float* __restrict__ bias,
                                                  float* __restrict__ outp)
{
    extern __shared__ __align__(1024) char dsm[];
    const uint32_t smem0 = s2u(dsm);

    const int tid = threadIdx.x, wid = tid>>5, lane = tid&31;
    const int row0 = blockIdx.y*128, col0 = blockIdx.x*128;

    const int wm = wid>>2, wn = wid&3;          // 4 x 4 warp grid
    const int m0 = wm*32, n0 = wn*32;
    const int ksrot = (wid>>2)&3;               // stagger warps WITHIN an SMSP

    const bf16 *Ah, *Al, *Bh, *Bl;
    if (EPI==1){ Ah=g_xh; Al=g_xl; Bh=g_w1h; Bl=g_w1l; }
    else       { Ah=g_Hh; Al=g_Hl; Bh=g_w2h; Bl=g_w2l; }
    const int TOT = KTOT/64;

    // ---- cp.async mapping: 512 threads, each thread 32B (2x16B) per 16KB tile ----
    const int lr = tid>>2;                      // tile row 0..127
    const int lc = (tid&3)*32;                  // byte col 0/32/64/96
    const uint32_t dstrel = lr*128 + (((lr&7)<<4) ^ lc);
    const int lce = lc>>1;                      // element offset
    const bf16* Arow_h = Ah + (size_t)(row0+lr)*KTOT + lce;
    const bf16* Arow_l = Al + (size_t)(row0+lr)*KTOT + lce;
    const bf16* Brow_h = Bh + (size_t)(col0+lr)*KTOT + lce;
    const bf16* Brow_l = Bl + (size_t)(col0+lr)*KTOT + lce;

    // ---- ldmatrix per-lane relative offsets (SW128 folded in) ----
    uint32_t relA[2], relB[2];
    {
        const int mat = lane>>3, r = lane&7;
        const int cfA = (mat>>1)*16;
#pragma unroll
        for (int mi=0; mi<2; ++mi){
            int row = m0 + mi*16 + (mat&1)*8 + r;
            relA[mi] = row*128 + ((((row&7)<<4) ^ cfA));
        }
        const int cfB = (mat&1)*16;
#pragma unroll
        for (int j=0; j<2; ++j){
            int row = n0 + j*16 + (mat>>1)*8 + r;
            relB[j] = row*128 + ((((row&7)<<4) ^ cfB));
        }
    }

    float acc[2][4][4];
#pragma unroll
    for (int mi=0;mi<2;mi++)
#pragma unroll
        for (int ni=0;ni<4;ni++)
#pragma unroll
            for (int q=0;q<4;q++) acc[mi][ni][q] = 0.f;

    // ---- issue chunk c into stage s: 4 tiles (Ah | Al | Bh | Bl) ----
    auto issue = [&](int c, int s){
        const int kk = c*64;
        const uint32_t d0 = smem0 + s*STAGE_BYTES + dstrel;
        const bf16* pah = Arow_h + kk;
        const bf16* pal = Arow_l + kk;
        const bf16* pbh = Brow_h + kk;
        const bf16* pbl = Brow_l + kk;
#pragma unroll
        for (int i=0;i<2;i++) cpasync16( d0           ^ (i*16), pah + i*8);
#pragma unroll
        for (int i=0;i<2;i++) cpasync16((d0 + 16384) ^ (i*16), pal + i*8);
#pragma unroll
        for (int i=0;i<2;i++) cpasync16((d0 + 32768) ^ (i*16), pbh + i*8);
#pragma unroll
        for (int i=0;i<2;i++) cpasync16((d0 + 49152) ^ (i*16), pbl + i*8);
        cp_commit();
    };

    issue(0, 0);
    issue(1, 1);

    for (int c = 0; c < TOT; ++c){
        if (c == TOT-1) asm volatile("cp.async.wait_group 0;" ::: "memory");
        else            asm volatile("cp.async.wait_group 1;" ::: "memory");
        __syncthreads();
        if (c+2 < TOT) issue(c+2, (c+2)%3);

        const uint32_t sAh = smem0 + (c%3)*STAGE_BYTES;
        const uint32_t sAl = sAh + 16384;
        const uint32_t sBh = sAh + 32768;
        const uint32_t sBl = sAh + 49152;
#pragma unroll
        for (int ksp=0; ksp<4; ++ksp){
            const uint32_t kx = ((uint32_t)((ksp + ksrot)&3))*32;
            uint32_t ah[2][4], al[2][4], bh[2][4], bl[2][4];
#pragma unroll
            for (int mi=0;mi<2;mi++) ldsm4(ah[mi], sAh + (relA[mi] ^ kx));
#pragma unroll
            for (int j=0;j<2;j++)    ldsm4(bh[j], sBh + (relB[j] ^ kx));
#pragma unroll
            for (int mi=0;mi<2;mi++) ldsm4(al[mi], sAl + (relA[mi] ^ kx));
#pragma unroll
            for (int j=0;j<2;j++)    ldsm4(bl[j], sBl + (relB[j] ^ kx));
            // pass0: Ah*Bh
#pragma unroll
            for (int mi=0;mi<2;mi++)
#pragma unroll
                for (int ni=0;ni<4;ni++)
                    mma16816(acc[mi][ni], ah[mi], bh[ni>>1][(ni&1)*2], bh[ni>>1][(ni&1)*2+1]);
            // pass1: Al*Bh
#pragma unroll
            for (int mi=0;mi<2;mi++)
#pragma unroll
                for (int ni=0;ni<4;ni++)
                    mma16816(acc[mi][ni], al[mi], bh[ni>>1][(ni&1)*2], bh[ni>>1][(ni&1)*2+1]);
            // pass2: Ah*Bl
#pragma unroll
            for (int mi=0;mi<2;mi++)
#pragma unroll
                for (int ni=0;ni<4;ni++)
                    mma16816(acc[mi][ni], ah[mi], bl[ni>>1][(ni&1)*2], bl[ni>>1][(ni&1)*2+1]);
        }
    }

    // ---- epilogue ----
    const int g = lane>>2, tig = lane&3;
    const int leaf = (col0 + n0) >> 6;      // 32-col warp tile never crosses a leaf
#pragma unroll
    for (int mi=0; mi<2; ++mi){
        const int ra = row0 + m0 + mi*16 + g;
        float mx0 = 0.f, mx1 = 0.f;
        if (EPI == 1){
            mx0 = g_mix[(size_t)ra*NLEAF + leaf];
            mx1 = g_mix[(size_t)(ra+8)*NLEAF + leaf];
        }
#pragma unroll
        for (int ni=0; ni<4; ++ni){
            const int col = col0 + n0 + ni*8 + tig*2;
            if (EPI == 1){
                const float b0v = bias[col], b1v = bias[col+1];
                float v00 = fmaxf(acc[mi][ni][0] + b0v, 0.f) * mx0;
                float v01 = fmaxf(acc[mi][ni][1] + b1v, 0.f) * mx0;
                float v10 = fmaxf(acc[mi][ni][2] + b0v, 0.f) * mx1;
                float v11 = fmaxf(acc[mi][ni][3] + b1v, 0.f) * mx1;
                __align__(4) bf16 h0[2], l0[2], h1[2], l1[2];
                bsplit(v00, h0[0], l0[0]); bsplit(v01, h0[1], l0[1]);
                bsplit(v10, h1[0], l1[0]); bsplit(v11, h1[1], l1[1]);
                *(uint32_t*)&g_Hh[(size_t)ra*HK + col]     = *(uint32_t*)h0;
                *(uint32_t*)&g_Hl[(size_t)ra*HK + col]     = *(uint32_t*)l0;
                *(uint32_t*)&g_Hh[(size_t)(ra+8)*HK + col] = *(uint32_t*)h1;
                *(uint32_t*)&g_Hl[(size_t)(ra+8)*HK + col] = *(uint32_t*)l1;
            } else {
                *(float2*)&outp[(size_t)ra*OUT_F + col]     = make_float2(acc[mi][ni][0], acc[mi][ni][1]);
                *(float2*)&outp[(size_t)(ra+8)*OUT_F + col] = make_float2(acc[mi][ni][2], acc[mi][ni][3]);
            }
        }
    }
}

// =====================================================================
extern "C" void kernel_launch(void* const* d_in, const int* in_sizes, int n_in,
                              void* d_out, int out_size) {
    const float* x   = (const float*)d_in[0];   // [4096,1024]
    const float* nw  = (const float*)d_in[1];   // [63,1024]
    const float* nb  = (const float*)d_in[2];   // [63,1]
    const float* w1s = (const float*)d_in[3];   // [64,1024,64]
    const float* b1s = (const float*)d_in[4];   // [64,64] flat = H column
    const float* w2s = (const float*)d_in[5];   // [64,64,512] flat = [4096,512]
    const float* b2s = (const float*)d_in[6];   // [64,512]
    float* out = (float*)d_out;                 // [4096,512]

    cudaFuncSetAttribute(gemm_mma<IN_F,1>, cudaFuncAttributeMaxDynamicSharedMemorySize, SMEMSZ);
    cudaFuncSetAttribute(gemm_mma<HK,2>,   cudaFuncAttributeMaxDynamicSharedMemorySize, SMEMSZ);

    mix_kernel <<<512,  256>>>(x, nw, nb);      // mix + convx fold
    conv_kernel<<<1544, 256>>>(w1s, w2s, b2s);  // weight conversions

    gemm_mma<IN_F,1><<<dim3(32,32), 512, SMEMSZ>>>(b1s, nullptr);   // H = relu(x@W1+b1)*mix
    gemm_mma<HK,2>  <<<dim3(4,32),  512, SMEMSZ>>>(nullptr, out);   // out = Hm@W2 + mix@b2
}

// round 16
// speedup vs baseline: 1.1391x; 1.1391x over previous
#include <cuda_runtime.h>
#include <cuda_bf16.h>
#include <cstdint>
#include <math.h>

typedef unsigned long long ull;
typedef __nv_bfloat16 bf16;

#define B_ROWS 4096
#define IN_F   1024
#define NLEAF  64
#define OUT_F  512
#define HK     4160                 /* 4096 H cols + 64 mixture cols (b2s fold) */
#define STAGE_BYTES 65536           /* Ah,Al,Bh,Bl tiles: 4 x 16KB per stage */
#define SMEMSZ (3*STAGE_BYTES)      /* 192KB, 1 CTA/SM */

// ---------------- device scratch ----------------
__device__ bf16 g_xh[B_ROWS*IN_F],  g_xl[B_ROWS*IN_F];
__device__ bf16 g_w1h[4096*1024],   g_w1l[4096*1024];   // [n=4096][k=1024]
__device__ bf16 g_w2h[512*HK],      g_w2l[512*HK];      // [o=512][k=4160]
__device__ bf16 g_Hh[(size_t)B_ROWS*HK], g_Hl[(size_t)B_ROWS*HK];
__device__ float g_mix[B_ROWS*NLEAF];

// ---------------- helpers ----------------
__device__ __forceinline__ void bsplit(float v, bf16 &h, bf16 &l){
    h = __float2bfloat16(v);
    l = __float2bfloat16(v - __bfloat162float(h));
}
__device__ __forceinline__ uint32_t s2u(const void* p){
    uint32_t a;
    asm("{ .reg .u64 t; cvta.to.shared.u64 t, %1; cvt.u32.u64 %0, t; }" : "=r"(a) : "l"(p));
    return a;
}
__device__ __forceinline__ void cpasync16(uint32_t dst, const void* src){
    asm volatile("cp.async.cg.shared.global [%0], [%1], 16;" :: "r"(dst), "l"(src) : "memory");
}
__device__ __forceinline__ void cp_commit(){ asm volatile("cp.async.commit_group;" ::: "memory"); }
__device__ __forceinline__ void ldsm4(uint32_t* r, uint32_t a){
    asm volatile("ldmatrix.sync.aligned.m8n8.x4.shared.b16 {%0,%1,%2,%3}, [%4];"
        : "=r"(r[0]), "=r"(r[1]), "=r"(r[2]), "=r"(r[3]) : "r"(a));
}
__device__ __forceinline__ void mma16816(float* c, const uint32_t* a, uint32_t b0, uint32_t b1){
    asm volatile("mma.sync.aligned.m16n8k16.row.col.f32.bf16.bf16.f32 "
        "{%0,%1,%2,%3}, {%4,%5,%6,%7}, {%8,%9}, {%0,%1,%2,%3};"
        : "+f"(c[0]), "+f"(c[1]), "+f"(c[2]), "+f"(c[3])
        : "r"(a[0]), "r"(a[1]), "r"(a[2]), "r"(a[3]), "r"(b0), "r"(b1));
}

// =====================================================================
// Merged conversion kernel (low-reg branches only; mix kept separate).
// blocks [0,4096): convx | [4096,5120): convw1 | [5120,5632): convw2 | [5632,5640): convtail
// =====================================================================
__global__ __launch_bounds__(256) void conv_kernel(
    const float* __restrict__ x,  const float* __restrict__ w1,
    const float* __restrict__ w2, const float* __restrict__ b2)
{
    __shared__ float s[64][65];
    const int blk = blockIdx.x, tid = threadIdx.x;

    if (blk < 4096){                       // ---- convx: 4096 blocks cover 1M float4 ----
        int i = blk*256 + tid;
        float4 v = ((const float4*)x)[i];
        __align__(8) bf16 h[4], l[4];
        bsplit(v.x,h[0],l[0]); bsplit(v.y,h[1],l[1]); bsplit(v.z,h[2],l[2]); bsplit(v.w,h[3],l[3]);
        *(ull*)&g_xh[(size_t)i*4] = *(ull*)h;
        *(ull*)&g_xl[(size_t)i*4] = *(ull*)l;
        return;
    }
    if (blk < 5120){                       // ---- convw1: [64,1024,64] -> [n][k] ----
        const int b = blk - 4096, kc = b & 15, l = b >> 4;
        const float* src = w1 + ((size_t)l*1024 + kc*64)*64;
        for (int u = tid; u < 4096; u += 256) s[u>>6][u&63] = src[u];
        __syncthreads();
        const int w = tid>>2, i0 = (tid&3)*16;
        __align__(16) bf16 hh[16], ll[16];
#pragma unroll
        for (int i=0;i<16;i++) bsplit(s[i0+i][w], hh[i], ll[i]);
        size_t off = (size_t)(l*64+w)*1024 + kc*64 + i0;
        *(uint4*)&g_w1h[off]   = ((uint4*)hh)[0]; *(uint4*)&g_w1h[off+8] = ((uint4*)hh)[1];
        *(uint4*)&g_w1l[off]   = ((uint4*)ll)[0]; *(uint4*)&g_w1l[off+8] = ((uint4*)ll)[1];
        return;
    }
    if (blk < 5632){                       // ---- convw2: [4096,512] -> [o][k] ----
        const int b = blk - 5120, ot = b & 7, rt = b >> 3;
        for (int u = tid; u < 4096; u += 256)
            s[u>>6][u&63] = w2[(size_t)(rt*64 + (u>>6))*512 + ot*64 + (u&63)];
        __syncthreads();
        const int o = tid>>2, i0 = (tid&3)*16;
        __align__(16) bf16 hh[16], ll[16];
#pragma unroll
        for (int i=0;i<16;i++) bsplit(s[i0+i][o], hh[i], ll[i]);
        size_t off = (size_t)(ot*64+o)*HK + rt*64 + i0;
        *(uint4*)&g_w2h[off]   = ((uint4*)hh)[0]; *(uint4*)&g_w2h[off+8] = ((uint4*)hh)[1];
        *(uint4*)&g_w2l[off]   = ((uint4*)ll)[0]; *(uint4*)&g_w2l[off+8] = ((uint4*)ll)[1];
        return;
    }
    {                                      // ---- convtail: b2 [64,512] -> w2t[o][4096+j] ----
        const int ot = blk - 5632;
        for (int u = tid; u < 4096; u += 256)
            s[u>>6][u&63] = b2[(size_t)(u>>6)*512 + ot*64 + (u&63)];
        __syncthreads();
        const int o = tid>>2, j0 = (tid&3)*16;
        __align__(16) bf16 hh[16], ll[16];
#pragma unroll
        for (int i=0;i<16;i++) bsplit(s[j0+i][o], hh[i], ll[i]);
        size_t off = (size_t)(ot*64+o)*HK + 4096 + j0;
        *(uint4*)&g_w2h[off]   = ((uint4*)hh)[0]; *(uint4*)&g_w2h[off+8] = ((uint4*)hh)[1];
        *(uint4*)&g_w2l[off]   = ((uint4*)ll)[0]; *(uint4*)&g_w2l[off+8] = ((uint4*)ll)[1];
    }
}

// =====================================================================
// Routing tree: 8 batch rows/block. Writes g_mix + hi/lo mixture tail of H.
// =====================================================================
__global__ __launch_bounds__(256) void mix_kernel(
    const float* __restrict__ x, const float* __restrict__ nw, const float* __restrict__ nb)
{
    __shared__ float xs[8*1024];
    __shared__ float lg[8][64];
    const int tid = threadIdx.x, warp = tid>>5, lane = tid&31;
    const int b0 = blockIdx.x * 8;

    for (int u = tid; u < 2048; u += 256)
        ((float4*)xs)[u] = ((const float4*)(x + (size_t)b0*IN_F))[u];
    __syncthreads();

    {
        float acc[8][8];
#pragma unroll
        for (int t=0;t<8;t++)
#pragma unroll
            for (int r=0;r<8;r++) acc[t][r] = 0.f;
        const float* wp[8];
#pragma unroll
        for (int t=0;t<8;t++){
            int nn = warp + 8*t;
            wp[t] = nw + (size_t)((nn < 63) ? nn : 0)*IN_F;
        }
        for (int j = 0; j < 32; ++j){
            const int o = lane + 32*j;
            float xv[8];
#pragma unroll
            for (int r=0;r<8;r++) xv[r] = xs[r*1024 + o];
#pragma unroll
            for (int t=0;t<8;t++){
                float wv = wp[t][o];
#pragma unroll
                for (int r=0;r<8;r++) acc[t][r] += xv[r]*wv;
            }
        }
#pragma unroll
        for (int t=0;t<8;t++){
            int nn = warp + 8*t;
#pragma unroll
            for (int r=0;r<8;r++){
                float s = acc[t][r];
#pragma unroll
                for (int o=16;o>0;o>>=1) s += __shfl_xor_sync(0xffffffffu, s, o);
                if (lane==0 && nn<63) lg[r][nn] = s + nb[nn];
            }
        }
    }
    __syncthreads();

#pragma unroll
    for (int p=0;p<2;p++){
        const int idx = tid + 256*p;
        const int r = idx>>6, l = idx&63;
        float m = 1.f;
#pragma unroll
        for (int d=0; d<6; ++d){
            int nidx = (1<<d) - 1 + (l >> (6-d));
            float sg = 1.f/(1.f + expf(-lg[r][nidx]));
            m *= ((l >> (5-d)) & 1) ? sg : (1.f - sg);
        }
        g_mix[(size_t)(b0+r)*NLEAF + l] = m;
        bf16 h, lo; bsplit(m, h, lo);
        g_Hh[(size_t)(b0+r)*HK + 4096 + l] = h;
        g_Hl[(size_t)(b0+r)*HK + 4096 + l] = lo;
    }
}

// =====================================================================
// HMMA split-bf16 GEMM. R13-proven config with ONE change: the cp.async
// prefetch burst for chunk c+2 is issued AFTER ks-step 0 (not before the
// ks loop), so its LDGSTS issue cost overlaps tensor-busy cycles instead
// of serializing in front of them.
// 512 threads, 16 warps (4/SMSP), CTA 128x128, warp 32x32, BK=64, 3-stage.
// Per chunk: acc += Ah*Bh + Al*Bh + Ah*Bl.
// EPI 1: bias+relu+mix -> Hh/Hl bf16.   EPI 2: plain fp32 store.
// =====================================================================
template<int KTOT, int EPI>
__global__ __launch_bounds__(512,1) void gemm_mma(const float* __restrict__ bias,
                                                  float* __restrict__ outp)
{
    extern __shared__ __align__(1024) char dsm[];
    const uint32_t smem0 = s2u(dsm);

    const int tid = threadIdx.x, wid = tid>>5, lane = tid&31;
    const int row0 = blockIdx.y*128, col0 = blockIdx.x*128;

    const int wm = wid>>2, wn = wid&3;          // 4 x 4 warp grid
    const int m0 = wm*32, n0 = wn*32;

    const bf16 *Ah, *Al, *Bh, *Bl;
    if (EPI==1){ Ah=g_xh; Al=g_xl; Bh=g_w1h; Bl=g_w1l; }
    else       { Ah=g_Hh; Al=g_Hl; Bh=g_w2h; Bl=g_w2l; }
    const int TOT = KTOT/64;

    // ---- cp.async mapping: 512 threads, each thread 32B (2x16B) per 16KB tile ----
    const int lr = tid>>2;                      // tile row 0..127
    const int lc = (tid&3)*32;                  // byte col 0/32/64/96
    const uint32_t dstrel = lr*128 + (((lr&7)<<4) ^ lc);
    const int lce = lc>>1;                      // element offset
    const bf16* Arow_h = Ah + (size_t)(row0+lr)*KTOT + lce;
    const bf16* Arow_l = Al + (size_t)(row0+lr)*KTOT + lce;
    const bf16* Brow_h = Bh + (size_t)(col0+lr)*KTOT + lce;
    const bf16* Brow_l = Bl + (size_t)(col0+lr)*KTOT + lce;

    // ---- ldmatrix per-lane relative offsets (SW128 folded in) ----
    uint32_t relA[2], relB[2];
    {
        const int mat = lane>>3, r = lane&7;
        const int cfA = (mat>>1)*16;
#pragma unroll
        for (int mi=0; mi<2; ++mi){
            int row = m0 + mi*16 + (mat&1)*8 + r;
            relA[mi] = row*128 + ((((row&7)<<4) ^ cfA));
        }
        const int cfB = (mat&1)*16;
#pragma unroll
        for (int j=0; j<2; ++j){
            int row = n0 + j*16 + (mat>>1)*8 + r;
            relB[j] = row*128 + ((((row&7)<<4) ^ cfB));
        }
    }

    float acc[2][4][4];
#pragma unroll
    for (int mi=0;mi<2;mi++)
#pragma unroll
        for (int ni=0;ni<4;ni++)
#pragma unroll
            for (int q=0;q<4;q++) acc[mi][ni][q] = 0.f;

    // ---- issue chunk c into stage s: 4 tiles (Ah | Al | Bh | Bl) ----
    auto issue = [&](int c, int s){
        const int kk = c*64;
        const uint32_t d0 = smem0 + s*STAGE_BYTES + dstrel;
        const bf16* pah = Arow_h + kk;
        const bf16* pal = Arow_l + kk;
        const bf16* pbh = Brow_h + kk;
        const bf16* pbl = Brow_l + kk;
#pragma unroll
        for (int i=0;i<2;i++) cpasync16( d0           ^ (i*16), pah + i*8);
#pragma unroll
        for (int i=0;i<2;i++) cpasync16((d0 + 16384) ^ (i*16), pal + i*8);
#pragma unroll
        for (int i=0;i<2;i++) cpasync16((d0 + 32768) ^ (i*16), pbh + i*8);
#pragma unroll
        for (int i=0;i<2;i++) cpasync16((d0 + 49152) ^ (i*16), pbl + i*8);
        cp_commit();
    };

    // ---- one ks step: 8 ldsm + 3 passes of 8 mma ----
    auto do_ks = [&](uint32_t sAh, uint32_t sAl, uint32_t sBh, uint32_t sBl, int ks){
        const uint32_t kx = (uint32_t)ks*32;
        uint32_t ah[2][4], al[2][4], bh[2][4], bl[2][4];
#pragma unroll
        for (int mi=0;mi<2;mi++) ldsm4(ah[mi], sAh + (relA[mi] ^ kx));
#pragma unroll
        for (int j=0;j<2;j++)    ldsm4(bh[j], sBh + (relB[j] ^ kx));
#pragma unroll
        for (int mi=0;mi<2;mi++) ldsm4(al[mi], sAl + (relA[mi] ^ kx));
#pragma unroll
        for (int j=0;j<2;j++)    ldsm4(bl[j], sBl + (relB[j] ^ kx));
        // pass0: Ah*Bh
#pragma unroll
        for (int mi=0;mi<2;mi++)
#pragma unroll
            for (int ni=0;ni<4;ni++)
                mma16816(acc[mi][ni], ah[mi], bh[ni>>1][(ni&1)*2], bh[ni>>1][(ni&1)*2+1]);
        // pass1: Al*Bh
#pragma unroll
        for (int mi=0;mi<2;mi++)
#pragma unroll
            for (int ni=0;ni<4;ni++)
                mma16816(acc[mi][ni], al[mi], bh[ni>>1][(ni&1)*2], bh[ni>>1][(ni&1)*2+1]);
        // pass2: Ah*Bl
#pragma unroll
        for (int mi=0;mi<2;mi++)
#pragma unroll
            for (int ni=0;ni<4;ni++)
                mma16816(acc[mi][ni], ah[mi], bl[ni>>1][(ni&1)*2], bl[ni>>1][(ni&1)*2+1]);
    };

    issue(0, 0);
    issue(1, 1);

    for (int c = 0; c < TOT; ++c){
        if (c == TOT-1) asm volatile("cp.async.wait_group 0;" ::: "memory");
        else            asm volatile("cp.async.wait_group 1;" ::: "memory");
        __syncthreads();

        const uint32_t sAh = smem0 + (c%3)*STAGE_BYTES;
        const uint32_t sAl = sAh + 16384;
        const uint32_t sBh = sAh + 32768;
        const uint32_t sBl = sAh + 49152;

        do_ks(sAh, sAl, sBh, sBl, 0);           // tensor pipe fills first...
        if (c+2 < TOT) issue(c+2, (c+2)%3);     // ...then prefetch burst overlaps it
        do_ks(sAh, sAl, sBh, sBl, 1);
        do_ks(sAh, sAl, sBh, sBl, 2);
        do_ks(sAh, sAl, sBh, sBl, 3);
    }

    // ---- epilogue ----
    const int g = lane>>2, tig = lane&3;
    const int leaf = (col0 + n0) >> 6;      // 32-col warp tile never crosses a leaf
#pragma unroll
    for (int mi=0; mi<2; ++mi){
        const int ra = row0 + m0 + mi*16 + g;
        float mx0 = 0.f, mx1 = 0.f;
        if (EPI == 1){
            mx0 = g_mix[(size_t)ra*NLEAF + leaf];
            mx1 = g_mix[(size_t)(ra+8)*NLEAF + leaf];
        }
#pragma unroll
        for (int ni=0; ni<4; ++ni){
            const int col = col0 + n0 + ni*8 + tig*2;
            if (EPI == 1){
                const float b0v = bias[col], b1v = bias[col+1];
                float v00 = fmaxf(acc[mi][ni][0] + b0v, 0.f) * mx0;
                float v01 = fmaxf(acc[mi][ni][1] + b1v, 0.f) * mx0;
                float v10 = fmaxf(acc[mi][ni][2] + b0v, 0.f) * mx1;
                float v11 = fmaxf(acc[mi][ni][3] + b1v, 0.f) * mx1;
                __align__(4) bf16 h0[2], l0[2], h1[2], l1[2];
                bsplit(v00, h0[0], l0[0]); bsplit(v01, h0[1], l0[1]);
                bsplit(v10, h1[0], l1[0]); bsplit(v11, h1[1], l1[1]);
                *(uint32_t*)&g_Hh[(size_t)ra*HK + col]     = *(uint32_t*)h0;
                *(uint32_t*)&g_Hl[(size_t)ra*HK + col]     = *(uint32_t*)l0;
                *(uint32_t*)&g_Hh[(size_t)(ra+8)*HK + col] = *(uint32_t*)h1;
                *(uint32_t*)&g_Hl[(size_t)(ra+8)*HK + col] = *(uint32_t*)l1;
            } else {
                *(float2*)&outp[(size_t)ra*OUT_F + col]     = make_float2(acc[mi][ni][0], acc[mi][ni][1]);
                *(float2*)&outp[(size_t)(ra+8)*OUT_F + col] = make_float2(acc[mi][ni][2], acc[mi][ni][3]);
            }
        }
    }
}

// =====================================================================
extern "C" void kernel_launch(void* const* d_in, const int* in_sizes, int n_in,
                              void* d_out, int out_size) {
    const float* x   = (const float*)d_in[0];   // [4096,1024]
    const float* nw  = (const float*)d_in[1];   // [63,1024]
    const float* nb  = (const float*)d_in[2];   // [63,1]
    const float* w1s = (const float*)d_in[3];   // [64,1024,64]
    const float* b1s = (const float*)d_in[4];   // [64,64] flat = H column
    const float* w2s = (const float*)d_in[5];   // [64,64,512] flat = [4096,512]
    const float* b2s = (const float*)d_in[6];   // [64,512]
    float* out = (float*)d_out;                 // [4096,512]

    cudaFuncSetAttribute(gemm_mma<IN_F,1>, cudaFuncAttributeMaxDynamicSharedMemorySize, SMEMSZ);
    cudaFuncSetAttribute(gemm_mma<HK,2>,   cudaFuncAttributeMaxDynamicSharedMemorySize, SMEMSZ);

    conv_kernel<<<5640, 256>>>(x, w1s, w2s, b2s);
    mix_kernel <<<512,  256>>>(x, nw, nb);

    gemm_mma<IN_F,1><<<dim3(32,32), 512, SMEMSZ>>>(b1s, nullptr);   // H = relu(x@W1+b1)*mix
    gemm_mma<HK,2>  <<<dim3(4,32),  512, SMEMSZ>>>(nullptr, out);   // out = Hm@W2 + mix@b2
}

// round 17
// speedup vs baseline: 1.1689x; 1.0261x over previous
#include <cuda_runtime.h>
#include <cuda_bf16.h>
#include <cstdint>
#include <math.h>

typedef unsigned long long ull;
typedef __nv_bfloat16 bf16;

#define B_ROWS 4096
#define IN_F   1024
#define NLEAF  64
#define OUT_F  512
#define HK     4160                 /* 4096 H cols + 64 mixture cols (b2s fold) */
#define STAGE_BYTES 65536           /* Ah,Al,Bh,Bl tiles: 4 x 16KB per stage */
#define SMEMSZ (3*STAGE_BYTES)      /* 192KB, 1 CTA/SM */

// ---------------- device scratch ----------------
__device__ bf16 g_xh[B_ROWS*IN_F],  g_xl[B_ROWS*IN_F];
__device__ bf16 g_w1h[4096*1024],   g_w1l[4096*1024];   // [n=4096][k=1024]
__device__ bf16 g_w2h[512*HK],      g_w2l[512*HK];      // [o=512][k=4160]
__device__ bf16 g_Hh[(size_t)B_ROWS*HK], g_Hl[(size_t)B_ROWS*HK];
__device__ float g_mix[B_ROWS*NLEAF];

// ---------------- helpers ----------------
__device__ __forceinline__ void bsplit(float v, bf16 &h, bf16 &l){
    h = __float2bfloat16(v);
    l = __float2bfloat16(v - __bfloat162float(h));
}
__device__ __forceinline__ uint32_t s2u(const void* p){
    uint32_t a;
    asm("{ .reg .u64 t; cvta.to.shared.u64 t, %1; cvt.u32.u64 %0, t; }" : "=r"(a) : "l"(p));
    return a;
}
__device__ __forceinline__ void cpasync16(uint32_t dst, const void* src){
    asm volatile("cp.async.cg.shared.global [%0], [%1], 16;" :: "r"(dst), "l"(src) : "memory");
}
__device__ __forceinline__ void cp_commit(){ asm volatile("cp.async.commit_group;" ::: "memory"); }
__device__ __forceinline__ void ldsm4(uint32_t* r, uint32_t a){
    asm volatile("ldmatrix.sync.aligned.m8n8.x4.shared.b16 {%0,%1,%2,%3}, [%4];"
        : "=r"(r[0]), "=r"(r[1]), "=r"(r[2]), "=r"(r[3]) : "r"(a));
}
__device__ __forceinline__ void mma16816(float* c, const uint32_t* a, uint32_t b0, uint32_t b1){
    asm volatile("mma.sync.aligned.m16n8k16.row.col.f32.bf16.bf16.f32 "
        "{%0,%1,%2,%3}, {%4,%5,%6,%7}, {%8,%9}, {%0,%1,%2,%3};"
        : "+f"(c[0]), "+f"(c[1]), "+f"(c[2]), "+f"(c[3])
        : "r"(a[0]), "r"(a[1]), "r"(a[2]), "r"(a[3]), "r"(b0), "r"(b1));
}

// =====================================================================
// Merged conversion kernel (low-reg branches only; mix kept separate).
// blocks [0,4096): convx | [4096,5120): convw1 | [5120,5632): convw2 | [5632,5640): convtail
// =====================================================================
__global__ __launch_bounds__(256) void conv_kernel(
    const float* __restrict__ x,  const float* __restrict__ w1,
    const float* __restrict__ w2, const float* __restrict__ b2)
{
    __shared__ float s[64][65];
    const int blk = blockIdx.x, tid = threadIdx.x;

    if (blk < 4096){                       // ---- convx: 4096 blocks cover 1M float4 ----
        int i = blk*256 + tid;
        float4 v = ((const float4*)x)[i];
        __align__(8) bf16 h[4], l[4];
        bsplit(v.x,h[0],l[0]); bsplit(v.y,h[1],l[1]); bsplit(v.z,h[2],l[2]); bsplit(v.w,h[3],l[3]);
        *(ull*)&g_xh[(size_t)i*4] = *(ull*)h;
        *(ull*)&g_xl[(size_t)i*4] = *(ull*)l;
        return;
    }
    if (blk < 5120){                       // ---- convw1: [64,1024,64] -> [n][k] ----
        const int b = blk - 4096, kc = b & 15, l = b >> 4;
        const float* src = w1 + ((size_t)l*1024 + kc*64)*64;
        for (int u = tid; u < 4096; u += 256) s[u>>6][u&63] = src[u];
        __syncthreads();
        const int w = tid>>2, i0 = (tid&3)*16;
        __align__(16) bf16 hh[16], ll[16];
#pragma unroll
        for (int i=0;i<16;i++) bsplit(s[i0+i][w], hh[i], ll[i]);
        size_t off = (size_t)(l*64+w)*1024 + kc*64 + i0;
        *(uint4*)&g_w1h[off]   = ((uint4*)hh)[0]; *(uint4*)&g_w1h[off+8] = ((uint4*)hh)[1];
        *(uint4*)&g_w1l[off]   = ((uint4*)ll)[0]; *(uint4*)&g_w1l[off+8] = ((uint4*)ll)[1];
        return;
    }
    if (blk < 5632){                       // ---- convw2: [4096,512] -> [o][k] ----
        const int b = blk - 5120, ot = b & 7, rt = b >> 3;
        for (int u = tid; u < 4096; u += 256)
            s[u>>6][u&63] = w2[(size_t)(rt*64 + (u>>6))*512 + ot*64 + (u&63)];
        __syncthreads();
        const int o = tid>>2, i0 = (tid&3)*16;
        __align__(16) bf16 hh[16], ll[16];
#pragma unroll
        for (int i=0;i<16;i++) bsplit(s[i0+i][o], hh[i], ll[i]);
        size_t off = (size_t)(ot*64+o)*HK + rt*64 + i0;
        *(uint4*)&g_w2h[off]   = ((uint4*)hh)[0]; *(uint4*)&g_w2h[off+8] = ((uint4*)hh)[1];
        *(uint4*)&g_w2l[off]   = ((uint4*)ll)[0]; *(uint4*)&g_w2l[off+8] = ((uint4*)ll)[1];
        return;
    }
    {                                      // ---- convtail: b2 [64,512] -> w2t[o][4096+j] ----
        const int ot = blk - 5632;
        for (int u = tid; u < 4096; u += 256)
            s[u>>6][u&63] = b2[(size_t)(u>>6)*512 + ot*64 + (u&63)];
        __syncthreads();
        const int o = tid>>2, j0 = (tid&3)*16;
        __align__(16) bf16 hh[16], ll[16];
#pragma unroll
        for (int i=0;i<16;i++) bsplit(s[j0+i][o], hh[i], ll[i]);
        size_t off = (size_t)(ot*64+o)*HK + 4096 + j0;
        *(uint4*)&g_w2h[off]   = ((uint4*)hh)[0]; *(uint4*)&g_w2h[off+8] = ((uint4*)hh)[1];
        *(uint4*)&g_w2l[off]   = ((uint4*)ll)[0]; *(uint4*)&g_w2l[off+8] = ((uint4*)ll)[1];
    }
}

// =====================================================================
// Routing tree: 8 batch rows/block. Writes g_mix + hi/lo mixture tail of H.
// =====================================================================
__global__ __launch_bounds__(256) void mix_kernel(
    const float* __restrict__ x, const float* __restrict__ nw, const float* __restrict__ nb)
{
    __shared__ float xs[8*1024];
    __shared__ float lg[8][64];
    const int tid = threadIdx.x, warp = tid>>5, lane = tid&31;
    const int b0 = blockIdx.x * 8;

    for (int u = tid; u < 2048; u += 256)
        ((float4*)xs)[u] = ((const float4*)(x + (size_t)b0*IN_F))[u];
    __syncthreads();

    {
        float acc[8][8];
#pragma unroll
        for (int t=0;t<8;t++)
#pragma unroll
            for (int r=0;r<8;r++) acc[t][r] = 0.f;
        const float* wp[8];
#pragma unroll
        for (int t=0;t<8;t++){
            int nn = warp + 8*t;
            wp[t] = nw + (size_t)((nn < 63) ? nn : 0)*IN_F;
        }
        for (int j = 0; j < 32; ++j){
            const int o = lane + 32*j;
            float xv[8];
#pragma unroll
            for (int r=0;r<8;r++) xv[r] = xs[r*1024 + o];
#pragma unroll
            for (int t=0;t<8;t++){
                float wv = wp[t][o];
#pragma unroll
                for (int r=0;r<8;r++) acc[t][r] += xv[r]*wv;
            }
        }
#pragma unroll
        for (int t=0;t<8;t++){
            int nn = warp + 8*t;
#pragma unroll
            for (int r=0;r<8;r++){
                float s = acc[t][r];
#pragma unroll
                for (int o=16;o>0;o>>=1) s += __shfl_xor_sync(0xffffffffu, s, o);
                if (lane==0 && nn<63) lg[r][nn] = s + nb[nn];
            }
        }
    }
    __syncthreads();

#pragma unroll
    for (int p=0;p<2;p++){
        const int idx = tid + 256*p;
        const int r = idx>>6, l = idx&63;
        float m = 1.f;
#pragma unroll
        for (int d=0; d<6; ++d){
            int nidx = (1<<d) - 1 + (l >> (6-d));
            float sg = 1.f/(1.f + expf(-lg[r][nidx]));
            m *= ((l >> (5-d)) & 1) ? sg : (1.f - sg);
        }
        g_mix[(size_t)(b0+r)*NLEAF + l] = m;
        bf16 h, lo; bsplit(m, h, lo);
        g_Hh[(size_t)(b0+r)*HK + 4096 + l] = h;
        g_Hl[(size_t)(b0+r)*HK + 4096 + l] = lo;
    }
}

// =====================================================================
// HMMA split-bf16 GEMM. R16 + two LSU-spreading changes:
//   (1) intra-ks ldsm staging: ah/bh before pass0, al mid-pass0, bl after
//       pass0 — first mma waits on 4 ldsm, not 8; al/bl latency hidden.
//   (2) prefetch burst split: A-tiles' cp.async after ks0, B-tiles'
//       cp.async + single commit after ks1 (same group accounting).
// 512 threads, 16 warps (4/SMSP), CTA 128x128, warp 32x32, BK=64, 3-stage.
// Per chunk: acc += Ah*Bh + Al*Bh + Ah*Bl (mma order IDENTICAL to R16).
// EPI 1: bias+relu+mix -> Hh/Hl bf16.   EPI 2: plain fp32 store.
// =====================================================================
template<int KTOT, int EPI>
__global__ __launch_bounds__(512,1) void gemm_mma(const float* __restrict__ bias,
                                                  float* __restrict__ outp)
{
    extern __shared__ __align__(1024) char dsm[];
    const uint32_t smem0 = s2u(dsm);

    const int tid = threadIdx.x, wid = tid>>5, lane = tid&31;
    const int row0 = blockIdx.y*128, col0 = blockIdx.x*128;

    const int wm = wid>>2, wn = wid&3;          // 4 x 4 warp grid
    const int m0 = wm*32, n0 = wn*32;

    const bf16 *Ah, *Al, *Bh, *Bl;
    if (EPI==1){ Ah=g_xh; Al=g_xl; Bh=g_w1h; Bl=g_w1l; }
    else       { Ah=g_Hh; Al=g_Hl; Bh=g_w2h; Bl=g_w2l; }
    const int TOT = KTOT/64;

    // ---- cp.async mapping: 512 threads, each thread 32B (2x16B) per 16KB tile ----
    const int lr = tid>>2;                      // tile row 0..127
    const int lc = (tid&3)*32;                  // byte col 0/32/64/96
    const uint32_t dstrel = lr*128 + (((lr&7)<<4) ^ lc);
    const int lce = lc>>1;                      // element offset
    const bf16* Arow_h = Ah + (size_t)(row0+lr)*KTOT + lce;
    const bf16* Arow_l = Al + (size_t)(row0+lr)*KTOT + lce;
    const bf16* Brow_h = Bh + (size_t)(col0+lr)*KTOT + lce;
    const bf16* Brow_l = Bl + (size_t)(col0+lr)*KTOT + lce;

    // ---- ldmatrix per-lane relative offsets (SW128 folded in) ----
    uint32_t relA[2], relB[2];
    {
        const int mat = lane>>3, r = lane&7;
        const int cfA = (mat>>1)*16;
#pragma unroll
        for (int mi=0; mi<2; ++mi){
            int row = m0 + mi*16 + (mat&1)*8 + r;
            relA[mi] = row*128 + ((((row&7)<<4) ^ cfA));
        }
        const int cfB = (mat&1)*16;
#pragma unroll
        for (int j=0; j<2; ++j){
            int row = n0 + j*16 + (mat>>1)*8 + r;
            relB[j] = row*128 + ((((row&7)<<4) ^ cfB));
        }
    }

    float acc[2][4][4];
#pragma unroll
    for (int mi=0;mi<2;mi++)
#pragma unroll
        for (int ni=0;ni<4;ni++)
#pragma unroll
            for (int q=0;q<4;q++) acc[mi][ni][q] = 0.f;

    // ---- prefetch halves: A tiles | B tiles (+commit) ----
    auto issueA = [&](int c, int s){
        const int kk = c*64;
        const uint32_t d0 = smem0 + s*STAGE_BYTES + dstrel;
#pragma unroll
        for (int i=0;i<2;i++) cpasync16( d0           ^ (i*16), Arow_h + kk + i*8);
#pragma unroll
        for (int i=0;i<2;i++) cpasync16((d0 + 16384) ^ (i*16), Arow_l + kk + i*8);
    };
    auto issueB = [&](int c, int s){
        const int kk = c*64;
        const uint32_t d0 = smem0 + s*STAGE_BYTES + dstrel;
#pragma unroll
        for (int i=0;i<2;i++) cpasync16((d0 + 32768) ^ (i*16), Brow_h + kk + i*8);
#pragma unroll
        for (int i=0;i<2;i++) cpasync16((d0 + 49152) ^ (i*16), Brow_l + kk + i*8);
        cp_commit();
    };

    // ---- one ks step with staged ldsm (mma order identical to R16) ----
    auto do_ks = [&](uint32_t sAh, uint32_t sAl, uint32_t sBh, uint32_t sBl, int ks){
        const uint32_t kx = (uint32_t)ks*32;
        uint32_t ah[2][4], al[2][4], bh[2][4], bl[2][4];
        // stage 1: operands for pass0
        ldsm4(ah[0], sAh + (relA[0] ^ kx));
        ldsm4(ah[1], sAh + (relA[1] ^ kx));
        ldsm4(bh[0], sBh + (relB[0] ^ kx));
        ldsm4(bh[1], sBh + (relB[1] ^ kx));
        // pass0 mi=0
#pragma unroll
        for (int ni=0;ni<4;ni++)
            mma16816(acc[0][ni], ah[0], bh[ni>>1][(ni&1)*2], bh[ni>>1][(ni&1)*2+1]);
        // stage 2: al for pass1 (hidden under pass0)
        ldsm4(al[0], sAl + (relA[0] ^ kx));
        ldsm4(al[1], sAl + (relA[1] ^ kx));
        // pass0 mi=1
#pragma unroll
        for (int ni=0;ni<4;ni++)
            mma16816(acc[1][ni], ah[1], bh[ni>>1][(ni&1)*2], bh[ni>>1][(ni&1)*2+1]);
        // stage 3: bl for pass2 (hidden under pass0/1)
        ldsm4(bl[0], sBl + (relB[0] ^ kx));
        ldsm4(bl[1], sBl + (relB[1] ^ kx));
        // pass1: Al*Bh
#pragma unroll
        for (int mi=0;mi<2;mi++)
#pragma unroll
            for (int ni=0;ni<4;ni++)
                mma16816(acc[mi][ni], al[mi], bh[ni>>1][(ni&1)*2], bh[ni>>1][(ni&1)*2+1]);
        // pass2: Ah*Bl
#pragma unroll
        for (int mi=0;mi<2;mi++)
#pragma unroll
            for (int ni=0;ni<4;ni++)
                mma16816(acc[mi][ni], ah[mi], bl[ni>>1][(ni&1)*2], bl[ni>>1][(ni&1)*2+1]);
    };

    // prologue: chunks 0 and 1 (full issue + commit each)
    issueA(0, 0); issueB(0, 0);
    issueA(1, 1); issueB(1, 1);

    for (int c = 0; c < TOT; ++c){
        if (c == TOT-1) asm volatile("cp.async.wait_group 0;" ::: "memory");
        else            asm volatile("cp.async.wait_group 1;" ::: "memory");
        __syncthreads();

        const uint32_t sAh = smem0 + (c%3)*STAGE_BYTES;
        const uint32_t sAl = sAh + 16384;
        const uint32_t sBh = sAh + 32768;
        const uint32_t sBl = sAh + 49152;

        do_ks(sAh, sAl, sBh, sBl, 0);
        if (c+2 < TOT) issueA(c+2, (c+2)%3);    // A prefetch under ks0's mma tail
        do_ks(sAh, sAl, sBh, sBl, 1);
        if (c+2 < TOT) issueB(c+2, (c+2)%3);    // B prefetch + commit under ks1's tail
        do_ks(sAh, sAl, sBh, sBl, 2);
        do_ks(sAh, sAl, sBh, sBl, 3);
    }

    // ---- epilogue ----
    const int g = lane>>2, tig = lane&3;
    const int leaf = (col0 + n0) >> 6;      // 32-col warp tile never crosses a leaf
#pragma unroll
    for (int mi=0; mi<2; ++mi){
        const int ra = row0 + m0 + mi*16 + g;
        float mx0 = 0.f, mx1 = 0.f;
        if (EPI == 1){
            mx0 = g_mix[(size_t)ra*NLEAF + leaf];
            mx1 = g_mix[(size_t)(ra+8)*NLEAF + leaf];
        }
#pragma unroll
        for (int ni=0; ni<4; ++ni){
            const int col = col0 + n0 + ni*8 + tig*2;
            if (EPI == 1){
                const float b0v = bias[col], b1v = bias[col+1];
                float v00 = fmaxf(acc[mi][ni][0] + b0v, 0.f) * mx0;
                float v01 = fmaxf(acc[mi][ni][1] + b1v, 0.f) * mx0;
                float v10 = fmaxf(acc[mi][ni][2] + b0v, 0.f) * mx1;
                float v11 = fmaxf(acc[mi][ni][3] + b1v, 0.f) * mx1;
                __align__(4) bf16 h0[2], l0[2], h1[2], l1[2];
                bsplit(v00, h0[0], l0[0]); bsplit(v01, h0[1], l0[1]);
                bsplit(v10, h1[0], l1[0]); bsplit(v11, h1[1], l1[1]);
                *(uint32_t*)&g_Hh[(size_t)ra*HK + col]     = *(uint32_t*)h0;
                *(uint32_t*)&g_Hl[(size_t)ra*HK + col]     = *(uint32_t*)l0;
                *(uint32_t*)&g_Hh[(size_t)(ra+8)*HK + col] = *(uint32_t*)h1;
                *(uint32_t*)&g_Hl[(size_t)(ra+8)*HK + col] = *(uint32_t*)l1;
            } else {
                *(float2*)&outp[(size_t)ra*OUT_F + col]     = make_float2(acc[mi][ni][0], acc[mi][ni][1]);
                *(float2*)&outp[(size_t)(ra+8)*OUT_F + col] = make_float2(acc[mi][ni][2], acc[mi][ni][3]);
            }
        }
    }
}

// =====================================================================
extern "C" void kernel_launch(void* const* d_in, const int* in_sizes, int n_in,
                              void* d_out, int out_size) {
    const float* x   = (const float*)d_in[0];   // [4096,1024]
    const float* nw  = (const float*)d_in[1];   // [63,1024]
    const float* nb  = (const float*)d_in[2];   // [63,1]
    const float* w1s = (const float*)d_in[3];   // [64,1024,64]
    const float* b1s = (const float*)d_in[4];   // [64,64] flat = H column
    const float* w2s = (const float*)d_in[5];   // [64,64,512] flat = [4096,512]
    const float* b2s = (const float*)d_in[6];   // [64,512]
    float* out = (float*)d_out;                 // [4096,512]

    cudaFuncSetAttribute(gemm_mma<IN_F,1>, cudaFuncAttributeMaxDynamicSharedMemorySize, SMEMSZ);
    cudaFuncSetAttribute(gemm_mma<HK,2>,   cudaFuncAttributeMaxDynamicSharedMemorySize, SMEMSZ);

    conv_kernel<<<5640, 256>>>(x, w1s, w2s, b2s);
    mix_kernel <<<512,  256>>>(x, nw, nb);

    gemm_mma<IN_F,1><<<dim3(32,32), 512, SMEMSZ>>>(b1s, nullptr);   // H = relu(x@W1+b1)*mix
    gemm_mma<HK,2>  <<<dim3(4,32),  512, SMEMSZ>>>(nullptr, out);   // out = Hm@W2 + mix@b2
}